// round 4
// baseline (speedup 1.0000x reference)
#include <cuda_runtime.h>
#include <cuda_bf16.h>
#include <cstdint>

typedef unsigned long long ull;

#define Bb   128
#define Tt   512
#define Ee   100
#define Uu   128
#define Kk   32
#define G4   512          // 4*U
#define BT   (Bb*Tt)      // 65536

// ---------------- scratch (static device allocations) ----------------
__device__ float g_zx[(size_t)2 * BT * G4];   // [dir][b*T+t][512]
__device__ float g_h [(size_t)2 * BT * Uu];   // [dir][b*T+t][128]
__device__ float g_em[(size_t)BT * Kk];       // [b*T+t][32]

// ---------------- fast math helpers ----------------
__device__ __forceinline__ float ex2f(float x){ float r; asm("ex2.approx.f32 %0, %1;" : "=f"(r) : "f"(x)); return r; }
__device__ __forceinline__ float lg2f(float x){ float r; asm("lg2.approx.f32 %0, %1;" : "=f"(r) : "f"(x)); return r; }
__device__ __forceinline__ float tanhfast(float x){ float r; asm("tanh.approx.f32 %0, %1;" : "=f"(r) : "f"(x)); return r; }
__device__ __forceinline__ float sigfast(float x){ return 0.5f * tanhfast(0.5f * x) + 0.5f; }
__device__ __forceinline__ float rcpf(float x){ float r; asm("rcp.approx.f32 %0, %1;" : "=f"(r) : "f"(x)); return r; }

// ---------------- f32x2 (FFMA2) helpers (kernel A/C) ----------------
__device__ __forceinline__ ull dup2(float x){
    ull r; asm("mov.b64 %0, {%1, %1};" : "=l"(r) : "f"(x)); return r;
}
__device__ __forceinline__ ull fma2(ull a, ull b, ull c){
    ull d; asm("fma.rn.f32x2 %0, %1, %2, %3;" : "=l"(d) : "l"(a), "l"(b), "l"(c)); return d;
}
__device__ __forceinline__ void unpk2(ull v, float& lo, float& hi){
    asm("mov.b64 {%0, %1}, %2;" : "=f"(lo), "=f"(hi) : "l"(v));
}
__device__ __forceinline__ void ldsv2(ull& a, ull& b, const void* p){
    unsigned s = (unsigned)__cvta_generic_to_shared(p);
    asm volatile("ld.shared.v2.u64 {%0, %1}, [%2];" : "=l"(a), "=l"(b) : "r"(s));
}
__device__ __forceinline__ __nv_bfloat162 asb2(unsigned u){
    return *reinterpret_cast<__nv_bfloat162*>(&u);
}

// =====================================================================
// Kernel A: zx[dir][bt][j] = emb[tokens[bt]] @ Wk_dir + b_dir
// grid (512, 8), block 256. Tile 128x128, 8x8 per thread, FFMA2.
// =====================================================================
#define XST 132
#define SMEM_A ((Ee*XST + Ee*128)*4 + 128*4 + 128*4)   // 105024

__global__ void __launch_bounds__(256, 2)
input_gemm(const int* __restrict__ tokens, const float* __restrict__ emb,
           const float* __restrict__ Wk_f, const float* __restrict__ b_f,
           const float* __restrict__ Wk_b, const float* __restrict__ b_b)
{
    extern __shared__ char sm[];
    float* xs_t = (float*)sm;                  // [100][132]
    float* ws   = xs_t + Ee * XST;             // [100][128]
    int*   tok  = (int*)(ws + Ee * 128);
    float* bs   = (float*)(tok + 128);

    const int tid = threadIdx.x;
    const int r0  = blockIdx.x * 128;
    const int c0  = blockIdx.y * 128;
    const int dir = c0 >> 9;
    const int cl  = c0 & 511;
    const float* Wk = dir ? Wk_b : Wk_f;
    const float* bv = dir ? b_b  : b_f;

    if (tid < 128) { tok[tid] = tokens[r0 + tid]; bs[tid] = bv[cl + tid]; }
    __syncthreads();

    for (int idx = tid; idx < 128 * Ee; idx += 256) {
        int r = idx / Ee, k = idx - r * Ee;
        xs_t[k * XST + r] = emb[(size_t)tok[r] * Ee + k];
    }
    for (int idx = tid; idx < Ee * 128; idx += 256) {
        int k = idx >> 7, c = idx & 127;
        ws[k * 128 + c] = Wk[k * G4 + cl + c];
    }
    __syncthreads();

    const int ty = tid >> 4, tx = tid & 15;
    const float* xrow = xs_t + 8 * ty;
    const float* wrow = ws + 8 * tx;

    ull acc[8][4];
#pragma unroll
    for (int i = 0; i < 8; i++)
#pragma unroll
        for (int j = 0; j < 4; j++) acc[i][j] = 0ull;

#pragma unroll 2
    for (int k = 0; k < Ee; k++) {
        ull w01, w23, w45, w67;
        ldsv2(w01, w23, wrow + k * 128);
        ldsv2(w45, w67, wrow + k * 128 + 4);
        float4 xa = *(const float4*)(xrow + k * XST);
        float4 xb = *(const float4*)(xrow + k * XST + 4);
        float xr[8] = {xa.x, xa.y, xa.z, xa.w, xb.x, xb.y, xb.z, xb.w};
#pragma unroll
        for (int i = 0; i < 8; i++) {
            ull xd = dup2(xr[i]);
            acc[i][0] = fma2(xd, w01, acc[i][0]);
            acc[i][1] = fma2(xd, w23, acc[i][1]);
            acc[i][2] = fma2(xd, w45, acc[i][2]);
            acc[i][3] = fma2(xd, w67, acc[i][3]);
        }
    }

#pragma unroll
    for (int i = 0; i < 8; i++) {
        int rg = r0 + 8 * ty + i;
        float v[8];
        unpk2(acc[i][0], v[0], v[1]);
        unpk2(acc[i][1], v[2], v[3]);
        unpk2(acc[i][2], v[4], v[5]);
        unpk2(acc[i][3], v[6], v[7]);
        float* dst = g_zx + ((size_t)dir * BT + rg) * G4 + cl + 8 * tx;
#pragma unroll
        for (int j = 0; j < 8; j++) dst[j] = v[j] + bs[8 * tx + j];
    }
}

// =====================================================================
// Kernel B: LSTM recurrence, quad-split, bf16 HFMA2 datapath.
// 128 blocks x 512 threads. Thread = (unit u, k-quarter q). Weights and
// h both live in smem as bf16x2; inner product is pure HFMA2 (no unpack).
// 4-way split accumulators bound bf16 accumulation error.
// =====================================================================
#define WSTRIDE 68                          // words per thread (64 + 4 pad)
#define HPW     72                          // per-batch h words (64 + 8 pad)
#define SMEM_B  (512*WSTRIDE*4 + 2*HPW*4)   // 139264 + 576 = 139840

__global__ void __launch_bounds__(512, 1)
lstm_rec(const float* __restrict__ Wr_f, const float* __restrict__ Wr_b)
{
    extern __shared__ char smem[];
    unsigned* w_s = (unsigned*)smem;                      // [512][68] bf16x2
    unsigned* h_s = (unsigned*)(smem + 512 * WSTRIDE * 4);// [2][72] bf16x2 words

    const int tid = threadIdx.x;
    const int u = tid >> 2, q = tid & 3;
    const int bx  = blockIdx.x;
    const int dir = bx >> 6;
    const int b0  = 2 * (bx & 63);
    const float* Wr = dir ? Wr_b : Wr_f;

    // stage weights: w_s[tid][g*16+kk] = bf16x2(Wr[32q+2kk][u+128g], Wr[32q+2kk+1][u+128g])
    {
        unsigned* wp = w_s + tid * WSTRIDE;
#pragma unroll
        for (int g = 0; g < 4; g++) {
            int c = u + 128 * g;
            for (int kk = 0; kk < 16; kk++) {
                int k = 32 * q + 2 * kk;
                __nv_bfloat162 pr = __floats2bfloat162_rn(Wr[k * G4 + c], Wr[(k + 1) * G4 + c]);
                wp[g * 16 + kk] = reinterpret_cast<unsigned&>(pr);
            }
        }
    }
    if (tid < 2 * HPW) h_s[tid] = 0u;
    __syncthreads();

    const uint4* wq  = (const uint4*)(w_s + tid * WSTRIDE);   // 16 uint4
    const uint4* hq0 = (const uint4*)(h_s) + 4 * q;           // batch0, words 16q..
    const uint4* hq1 = (const uint4*)(h_s + HPW) + 4 * q;     // batch1
    __nv_bfloat16* hb = (__nv_bfloat16*)h_s;                  // write view

    const bool fin = (q < 2);
    const int bb = b0 + (q & 1);
    const float* zxp = g_zx + ((size_t)dir * BT + (size_t)bb * Tt) * G4;
    float* hout = g_h + ((size_t)dir * BT + (size_t)bb * Tt) * Uu;
    const unsigned full = 0xffffffffu;

    float c_reg = 0.f;
    int t0 = dir ? (Tt - 1) : 0;
    float pz0 = 0.f, pz1 = 0.f, pz2 = 0.f, pz3 = 0.f;
    if (fin) {
        const float* zr = zxp + (size_t)t0 * G4;
        pz0 = zr[u]; pz1 = zr[u + 128]; pz2 = zr[u + 256]; pz3 = zr[u + 384];
    }

    const __nv_bfloat162 bz = __float2bfloat162_rn(0.f);

    for (int step = 0; step < Tt; step++) {
        const int t = dir ? (Tt - 1 - step) : step;
        float cz0 = pz0, cz1 = pz1, cz2 = pz2, cz3 = pz3;
        int tn = dir ? (t - 1) : (t + 1);
        tn = min(max(tn, 0), Tt - 1);
        if (fin) {
            const float* zr = zxp + (size_t)tn * G4;
            pz0 = zr[u]; pz1 = zr[u + 128]; pz2 = zr[u + 256]; pz3 = zr[u + 384];
        }

        // [g][batch], even/odd kk splits
        __nv_bfloat162 ae[4][2], ao[4][2];
#pragma unroll
        for (int g = 0; g < 4; g++) { ae[g][0] = bz; ae[g][1] = bz; ao[g][0] = bz; ao[g][1] = bz; }

#pragma unroll
        for (int p = 0; p < 4; p++) {
            uint4 hv0 = hq0[p];
            uint4 hv1 = hq1[p];
            __nv_bfloat162 h0x = asb2(hv0.x), h0y = asb2(hv0.y), h0z = asb2(hv0.z), h0w = asb2(hv0.w);
            __nv_bfloat162 h1x = asb2(hv1.x), h1y = asb2(hv1.y), h1z = asb2(hv1.z), h1w = asb2(hv1.w);
#pragma unroll
            for (int g = 0; g < 4; g++) {
                uint4 wv = wq[g * 4 + p];
                ae[g][0] = __hfma2(asb2(wv.x), h0x, ae[g][0]);
                ao[g][0] = __hfma2(asb2(wv.y), h0y, ao[g][0]);
                ae[g][0] = __hfma2(asb2(wv.z), h0z, ae[g][0]);
                ao[g][0] = __hfma2(asb2(wv.w), h0w, ao[g][0]);
                ae[g][1] = __hfma2(asb2(wv.x), h1x, ae[g][1]);
                ao[g][1] = __hfma2(asb2(wv.y), h1y, ao[g][1]);
                ae[g][1] = __hfma2(asb2(wv.z), h1z, ae[g][1]);
                ao[g][1] = __hfma2(asb2(wv.w), h1w, ao[g][1]);
            }
        }

        float d0[4], d1[4];
#pragma unroll
        for (int g = 0; g < 4; g++) {
            float2 fa = __bfloat1622float2(ae[g][0]);
            float2 fb = __bfloat1622float2(ao[g][0]);
            d0[g] = (fa.x + fa.y) + (fb.x + fb.y);
            float2 fc = __bfloat1622float2(ae[g][1]);
            float2 fd = __bfloat1622float2(ao[g][1]);
            d1[g] = (fc.x + fc.y) + (fd.x + fd.y);
        }
#pragma unroll
        for (int o = 1; o <= 2; o <<= 1) {
#pragma unroll
            for (int g = 0; g < 4; g++) {
                d0[g] += __shfl_xor_sync(full, d0[g], o);
                d1[g] += __shfl_xor_sync(full, d1[g], o);
            }
        }

        if (fin) {
            float zi = ((q == 0) ? d0[0] : d1[0]) + cz0;
            float zf = ((q == 0) ? d0[1] : d1[1]) + cz1;
            float zg = ((q == 0) ? d0[2] : d1[2]) + cz2;
            float zo = ((q == 0) ? d0[3] : d1[3]) + cz3;
            c_reg = sigfast(zf) * c_reg + sigfast(zi) * tanhfast(zg);
            float h = sigfast(zo) * tanhfast(c_reg);
            hb[q * (2 * HPW) + u] = __float2bfloat16(h);
            hout[(size_t)t * Uu + u] = h;
        }
        __syncthreads();
    }
}

// =====================================================================
// Kernel C: em = [h_f, h_b] @ crf_kernel + bias.  grid BT/8, block 256.
// =====================================================================
#define CKP 260
__global__ void em_gemm(const float* __restrict__ ck, const float* __restrict__ cb)
{
    __shared__ float ck_t[Kk][CKP];
    __shared__ float hs[8][2 * Uu];
    __shared__ float cb_s[Kk];

    const int tid = threadIdx.x;
    const int bt0 = blockIdx.x * 8;

    for (int idx = tid; idx < 2 * Uu * Kk; idx += 256) {
        int uu = idx >> 5, k = idx & 31;
        ck_t[k][uu] = ck[idx];
    }
    if (tid < Kk) cb_s[tid] = cb[tid];
    for (int idx = tid; idx < 8 * 2 * Uu; idx += 256) {
        int r = idx >> 8, uu = idx & 255;
        hs[r][uu] = (uu < Uu) ? g_h[(size_t)(bt0 + r) * Uu + uu]
                              : g_h[(size_t)BT * Uu + (size_t)(bt0 + r) * Uu + (uu - Uu)];
    }
    __syncthreads();

    const int r = tid >> 5, k = tid & 31;
    ull acc0 = 0, acc1 = 0;
#pragma unroll 8
    for (int uu = 0; uu < 2 * Uu; uu += 4) {
        ull h01, h23, c01, c23;
        ldsv2(h01, h23, &hs[r][uu]);
        ldsv2(c01, c23, &ck_t[k][uu]);
        acc0 = fma2(h01, c01, acc0);
        acc1 = fma2(h23, c23, acc1);
    }
    float x0, x1, y0, y1;
    unpk2(acc0, x0, x1); unpk2(acc1, y0, y1);
    g_em[(size_t)(bt0 + r) * Kk + k] = ((x0 + x1) + (y0 + y1)) + cb_s[k];
}

// =====================================================================
// Kernel D: CRF logZ, linear space + shfl dot + lazy renorm (every 8).
// Per step: p_k = (sum_j shfl(v,j)*E[j][k]) * u_k ; no exp/log/div on
// the per-step chain. Growth <= ~2^10/step -> 8 steps safely < 2^91.
// =====================================================================
__global__ void crf_logz(const float* __restrict__ trans, float* __restrict__ out)
{
    const float L2E = 1.4426950408889634f, LN2 = 0.6931471805599453f;
    const int b = blockIdx.x;
    const int k = threadIdx.x;
    const unsigned full = 0xffffffffu;

    float Ecol[Kk];
#pragma unroll
    for (int jj = 0; jj < Kk; jj++)
        Ecol[jj] = ex2f(trans[jj * Kk + k] * L2E);

    const float* em = g_em + (size_t)b * Tt * Kk;

    float uring[8];
#pragma unroll
    for (int i = 0; i < 8; i++)
        uring[i] = ex2f(em[(size_t)(1 + i) * Kk + k] * L2E);

    float e0 = em[k];
    float m0 = __shfl_sync(full, e0, 0);
    float v  = ex2f((e0 - m0) * L2E);
    float Ml = m0 * L2E;

#pragma unroll 8
    for (int t = 1; t < Tt; t++) {
        float s0 = 0.f, s1 = 0.f, s2 = 0.f, s3 = 0.f;
#pragma unroll
        for (int j = 0; j < Kk; j += 4) {
            s0 += __shfl_sync(full, v, j    ) * Ecol[j    ];
            s1 += __shfl_sync(full, v, j + 1) * Ecol[j + 1];
            s2 += __shfl_sync(full, v, j + 2) * Ecol[j + 2];
            s3 += __shfl_sync(full, v, j + 3) * Ecol[j + 3];
        }
        float p = ((s0 + s1) + (s2 + s3)) * uring[(t - 1) & 7];
        int tp = t + 8;
        uring[(t - 1) & 7] = (tp < Tt) ? ex2f(em[(size_t)tp * Kk + k] * L2E) : 1.0f;
        v = p;
        if ((t & 7) == 0) {                      // lazy renormalization
            float p0 = __shfl_sync(full, v, 0);
            v *= rcpf(p0);
            Ml += lg2f(p0);
        }
    }

    float sv = v;
#pragma unroll
    for (int o = 16; o; o >>= 1) sv += __shfl_xor_sync(full, sv, o);
    if (k == 0) out[b] = (Ml + lg2f(sv)) * LN2;
}

// =====================================================================
extern "C" void kernel_launch(void* const* d_in, const int* in_sizes, int n_in,
                              void* d_out, int out_size)
{
    const int*   tokens = (const int*)  d_in[0];
    const float* emb    = (const float*)d_in[1];
    const float* Wk_f   = (const float*)d_in[2];
    const float* Wr_f   = (const float*)d_in[3];
    const float* b_f    = (const float*)d_in[4];
    const float* Wk_b   = (const float*)d_in[5];
    const float* Wr_b   = (const float*)d_in[6];
    const float* b_b    = (const float*)d_in[7];
    const float* ck     = (const float*)d_in[8];
    const float* cb     = (const float*)d_in[9];
    const float* trans  = (const float*)d_in[10];
    float* out = (float*)d_out;

    cudaFuncSetAttribute(input_gemm, cudaFuncAttributeMaxDynamicSharedMemorySize, SMEM_A);
    cudaFuncSetAttribute(lstm_rec,   cudaFuncAttributeMaxDynamicSharedMemorySize, SMEM_B);

    input_gemm<<<dim3(BT / 128, 8), 256, SMEM_A>>>(tokens, emb, Wk_f, b_f, Wk_b, b_b);
    lstm_rec<<<128, 512, SMEM_B>>>(Wr_f, Wr_b);
    em_gemm<<<BT / 8, 256>>>(ck, cb);
    crf_logz<<<Bb, 32>>>(trans, out);
}

// round 5
// speedup vs baseline: 1.3368x; 1.3368x over previous
#include <cuda_runtime.h>
#include <cuda_bf16.h>
#include <cstdint>

typedef unsigned long long ull;

#define Bb   128
#define Tt   512
#define Ee   100
#define Uu   128
#define Kk   32
#define G4   512          // 4*U
#define BT   (Bb*Tt)      // 65536

// ---------------- scratch (static device allocations) ----------------
__device__ float g_zx[(size_t)2 * BT * G4];   // [dir][b*T+t][512]
__device__ float g_h [(size_t)2 * BT * Uu];   // [dir][b*T+t][128]
__device__ float g_em[(size_t)BT * Kk];       // [b*T+t][32]

// ---------------- fast math helpers ----------------
__device__ __forceinline__ float ex2f(float x){ float r; asm("ex2.approx.f32 %0, %1;" : "=f"(r) : "f"(x)); return r; }
__device__ __forceinline__ float lg2f(float x){ float r; asm("lg2.approx.f32 %0, %1;" : "=f"(r) : "f"(x)); return r; }
__device__ __forceinline__ float tanhfast(float x){ float r; asm("tanh.approx.f32 %0, %1;" : "=f"(r) : "f"(x)); return r; }
__device__ __forceinline__ float sigfast(float x){ return 0.5f * tanhfast(0.5f * x) + 0.5f; }
__device__ __forceinline__ float rcpf(float x){ float r; asm("rcp.approx.f32 %0, %1;" : "=f"(r) : "f"(x)); return r; }

// ---------------- f32x2 (FFMA2) helpers (kernel A/C) ----------------
__device__ __forceinline__ ull dup2(float x){
    ull r; asm("mov.b64 %0, {%1, %1};" : "=l"(r) : "f"(x)); return r;
}
__device__ __forceinline__ ull fma2(ull a, ull b, ull c){
    ull d; asm("fma.rn.f32x2 %0, %1, %2, %3;" : "=l"(d) : "l"(a), "l"(b), "l"(c)); return d;
}
__device__ __forceinline__ void unpk2(ull v, float& lo, float& hi){
    asm("mov.b64 {%0, %1}, %2;" : "=f"(lo), "=f"(hi) : "l"(v));
}
__device__ __forceinline__ void ldsv2(ull& a, ull& b, const void* p){
    unsigned s = (unsigned)__cvta_generic_to_shared(p);
    asm volatile("ld.shared.v2.u64 {%0, %1}, [%2];" : "=l"(a), "=l"(b) : "r"(s));
}
__device__ __forceinline__ __nv_bfloat162 asb2(unsigned u){
    return *reinterpret_cast<__nv_bfloat162*>(&u);
}

// =====================================================================
// Kernel A: zx[dir][bt][j] = emb[tokens[bt]] @ Wk_dir + b_dir
// grid (512, 8), block 256. Tile 128x128, 8x8 per thread, FFMA2.
// =====================================================================
#define XST 132
#define SMEM_A ((Ee*XST + Ee*128)*4 + 128*4 + 128*4)   // 105024

__global__ void __launch_bounds__(256, 2)
input_gemm(const int* __restrict__ tokens, const float* __restrict__ emb,
           const float* __restrict__ Wk_f, const float* __restrict__ b_f,
           const float* __restrict__ Wk_b, const float* __restrict__ b_b)
{
    extern __shared__ char sm[];
    float* xs_t = (float*)sm;                  // [100][132]
    float* ws   = xs_t + Ee * XST;             // [100][128]
    int*   tok  = (int*)(ws + Ee * 128);
    float* bs   = (float*)(tok + 128);

    const int tid = threadIdx.x;
    const int r0  = blockIdx.x * 128;
    const int c0  = blockIdx.y * 128;
    const int dir = c0 >> 9;
    const int cl  = c0 & 511;
    const float* Wk = dir ? Wk_b : Wk_f;
    const float* bv = dir ? b_b  : b_f;

    if (tid < 128) { tok[tid] = tokens[r0 + tid]; bs[tid] = bv[cl + tid]; }
    __syncthreads();

    for (int idx = tid; idx < 128 * Ee; idx += 256) {
        int r = idx / Ee, k = idx - r * Ee;
        xs_t[k * XST + r] = emb[(size_t)tok[r] * Ee + k];
    }
    for (int idx = tid; idx < Ee * 128; idx += 256) {
        int k = idx >> 7, c = idx & 127;
        ws[k * 128 + c] = Wk[k * G4 + cl + c];
    }
    __syncthreads();

    const int ty = tid >> 4, tx = tid & 15;
    const float* xrow = xs_t + 8 * ty;
    const float* wrow = ws + 8 * tx;

    ull acc[8][4];
#pragma unroll
    for (int i = 0; i < 8; i++)
#pragma unroll
        for (int j = 0; j < 4; j++) acc[i][j] = 0ull;

#pragma unroll 2
    for (int k = 0; k < Ee; k++) {
        ull w01, w23, w45, w67;
        ldsv2(w01, w23, wrow + k * 128);
        ldsv2(w45, w67, wrow + k * 128 + 4);
        float4 xa = *(const float4*)(xrow + k * XST);
        float4 xb = *(const float4*)(xrow + k * XST + 4);
        float xr[8] = {xa.x, xa.y, xa.z, xa.w, xb.x, xb.y, xb.z, xb.w};
#pragma unroll
        for (int i = 0; i < 8; i++) {
            ull xd = dup2(xr[i]);
            acc[i][0] = fma2(xd, w01, acc[i][0]);
            acc[i][1] = fma2(xd, w23, acc[i][1]);
            acc[i][2] = fma2(xd, w45, acc[i][2]);
            acc[i][3] = fma2(xd, w67, acc[i][3]);
        }
    }

#pragma unroll
    for (int i = 0; i < 8; i++) {
        int rg = r0 + 8 * ty + i;
        float v[8];
        unpk2(acc[i][0], v[0], v[1]);
        unpk2(acc[i][1], v[2], v[3]);
        unpk2(acc[i][2], v[4], v[5]);
        unpk2(acc[i][3], v[6], v[7]);
        float* dst = g_zx + ((size_t)dir * BT + rg) * G4 + cl + 8 * tx;
#pragma unroll
        for (int j = 0; j < 8; j++) dst[j] = v[j] + bs[8 * tx + j];
    }
}

// =====================================================================
// Kernel B: LSTM recurrence, quad-split, WEIGHTS IN REGISTERS.
// 128 blocks x 512 threads. Thread = (unit u, k-quarter q) holds its
// 64 bf16x2 weight words in registers; only the bf16 h vector lives in
// smem (stride-20-word quarters -> conflict-free broadcast LDS.128).
// Per-step smem traffic: ~0 weights (was 128KB via crossbar).
// =====================================================================
#define WSTAGE 68                        // staging words per thread
#define HB     80                        // words per batch (4 quarters x 20)
#define SMEM_B (512*WSTAGE*4)            // 139264 (staging; reused for h)

__global__ void __launch_bounds__(512, 1)
lstm_rec(const float* __restrict__ Wr_f, const float* __restrict__ Wr_b)
{
    extern __shared__ char smem[];
    unsigned* w_s = (unsigned*)smem;     // staging [512][68] bf16x2

    const int tid = threadIdx.x;
    const int u = tid >> 2, q = tid & 3;
    const int bx  = blockIdx.x;
    const int dir = bx >> 6;
    const int b0  = 2 * (bx & 63);
    const float* Wr = dir ? Wr_b : Wr_f;

    // stage weights coalesced-ish into smem, then pull into registers
    {
        unsigned* wp = w_s + tid * WSTAGE;
#pragma unroll
        for (int g = 0; g < 4; g++) {
            int c = u + 128 * g;
            for (int kk = 0; kk < 16; kk++) {
                int k = 32 * q + 2 * kk;
                __nv_bfloat162 pr = __floats2bfloat162_rn(Wr[k * G4 + c], Wr[(k + 1) * G4 + c]);
                wp[g * 16 + kk] = reinterpret_cast<unsigned&>(pr);
            }
        }
    }
    __syncthreads();
    uint4 wreg[16];                                   // 64 regs: weights live here
    {
        const uint4* wq = (const uint4*)(w_s + tid * WSTAGE);
#pragma unroll
        for (int i = 0; i < 16; i++) wreg[i] = wq[i];
    }
    __syncthreads();                                  // all reads done; reuse smem

    unsigned* h_s = (unsigned*)smem;                  // [2][80] words (bf16x2)
    __nv_bfloat16* hb = (__nv_bfloat16*)smem;         // bf16 write view
    if (tid < 2 * HB) h_s[tid] = 0u;
    __syncthreads();

    const uint4* hq0 = (const uint4*)(h_s + 20 * q);       // batch0, quarter q
    const uint4* hq1 = (const uint4*)(h_s + HB + 20 * q);  // batch1

    const bool fin = (q < 2);
    const int bb = b0 + (q & 1);
    const float* zxp = g_zx + ((size_t)dir * BT + (size_t)bb * Tt) * G4;
    float* hout = g_h + ((size_t)dir * BT + (size_t)bb * Tt) * Uu;
    const unsigned full = 0xffffffffu;

    float c_reg = 0.f;
    int t0 = dir ? (Tt - 1) : 0;
    float pz0 = 0.f, pz1 = 0.f, pz2 = 0.f, pz3 = 0.f;
    if (fin) {
        const float* zr = zxp + (size_t)t0 * G4;
        pz0 = zr[u]; pz1 = zr[u + 128]; pz2 = zr[u + 256]; pz3 = zr[u + 384];
    }

    const __nv_bfloat162 bz = __float2bfloat162_rn(0.f);
    // bf16 write index for this thread's h (unit u, batch q when fin)
    const int hwidx = (q & 1) * (2 * HB) + (u >> 5) * 40 + (u & 31);

    for (int step = 0; step < Tt; step++) {
        const int t = dir ? (Tt - 1 - step) : step;
        float cz0 = pz0, cz1 = pz1, cz2 = pz2, cz3 = pz3;
        int tn = dir ? (t - 1) : (t + 1);
        tn = min(max(tn, 0), Tt - 1);
        if (fin) {
            const float* zr = zxp + (size_t)tn * G4;
            pz0 = zr[u]; pz1 = zr[u + 128]; pz2 = zr[u + 256]; pz3 = zr[u + 384];
        }

        __nv_bfloat162 ae[4][2], ao[4][2];
#pragma unroll
        for (int g = 0; g < 4; g++) { ae[g][0] = bz; ae[g][1] = bz; ao[g][0] = bz; ao[g][1] = bz; }

#pragma unroll
        for (int p = 0; p < 4; p++) {
            uint4 hv0 = hq0[p];
            uint4 hv1 = hq1[p];
            __nv_bfloat162 h0x = asb2(hv0.x), h0y = asb2(hv0.y), h0z = asb2(hv0.z), h0w = asb2(hv0.w);
            __nv_bfloat162 h1x = asb2(hv1.x), h1y = asb2(hv1.y), h1z = asb2(hv1.z), h1w = asb2(hv1.w);
#pragma unroll
            for (int g = 0; g < 4; g++) {
                uint4 wv = wreg[g * 4 + p];
                ae[g][0] = __hfma2(asb2(wv.x), h0x, ae[g][0]);
                ao[g][0] = __hfma2(asb2(wv.y), h0y, ao[g][0]);
                ae[g][0] = __hfma2(asb2(wv.z), h0z, ae[g][0]);
                ao[g][0] = __hfma2(asb2(wv.w), h0w, ao[g][0]);
                ae[g][1] = __hfma2(asb2(wv.x), h1x, ae[g][1]);
                ao[g][1] = __hfma2(asb2(wv.y), h1y, ao[g][1]);
                ae[g][1] = __hfma2(asb2(wv.z), h1z, ae[g][1]);
                ao[g][1] = __hfma2(asb2(wv.w), h1w, ao[g][1]);
            }
        }

        float d0[4], d1[4];
#pragma unroll
        for (int g = 0; g < 4; g++) {
            float2 fa = __bfloat1622float2(ae[g][0]);
            float2 fb = __bfloat1622float2(ao[g][0]);
            d0[g] = (fa.x + fa.y) + (fb.x + fb.y);
            float2 fc = __bfloat1622float2(ae[g][1]);
            float2 fd = __bfloat1622float2(ao[g][1]);
            d1[g] = (fc.x + fc.y) + (fd.x + fd.y);
        }
#pragma unroll
        for (int o = 1; o <= 2; o <<= 1) {
#pragma unroll
            for (int g = 0; g < 4; g++) {
                d0[g] += __shfl_xor_sync(full, d0[g], o);
                d1[g] += __shfl_xor_sync(full, d1[g], o);
            }
        }

        if (fin) {
            float zi = ((q == 0) ? d0[0] : d1[0]) + cz0;
            float zf = ((q == 0) ? d0[1] : d1[1]) + cz1;
            float zg = ((q == 0) ? d0[2] : d1[2]) + cz2;
            float zo = ((q == 0) ? d0[3] : d1[3]) + cz3;
            c_reg = sigfast(zf) * c_reg + sigfast(zi) * tanhfast(zg);
            float h = sigfast(zo) * tanhfast(c_reg);
            hb[hwidx] = __float2bfloat16(h);
            hout[(size_t)t * Uu + u] = h;
        }
        __syncthreads();
    }
}

// =====================================================================
// Kernel C: em = [h_f, h_b] @ crf_kernel + bias.  grid BT/8, block 256.
// =====================================================================
#define CKP 260
__global__ void em_gemm(const float* __restrict__ ck, const float* __restrict__ cb)
{
    __shared__ float ck_t[Kk][CKP];
    __shared__ float hs[8][2 * Uu];
    __shared__ float cb_s[Kk];

    const int tid = threadIdx.x;
    const int bt0 = blockIdx.x * 8;

    for (int idx = tid; idx < 2 * Uu * Kk; idx += 256) {
        int uu = idx >> 5, k = idx & 31;
        ck_t[k][uu] = ck[idx];
    }
    if (tid < Kk) cb_s[tid] = cb[tid];
    for (int idx = tid; idx < 8 * 2 * Uu; idx += 256) {
        int r = idx >> 8, uu = idx & 255;
        hs[r][uu] = (uu < Uu) ? g_h[(size_t)(bt0 + r) * Uu + uu]
                              : g_h[(size_t)BT * Uu + (size_t)(bt0 + r) * Uu + (uu - Uu)];
    }
    __syncthreads();

    const int r = tid >> 5, k = tid & 31;
    ull acc0 = 0, acc1 = 0;
#pragma unroll 8
    for (int uu = 0; uu < 2 * Uu; uu += 4) {
        ull h01, h23, c01, c23;
        ldsv2(h01, h23, &hs[r][uu]);
        ldsv2(c01, c23, &ck_t[k][uu]);
        acc0 = fma2(h01, c01, acc0);
        acc1 = fma2(h23, c23, acc1);
    }
    float x0, x1, y0, y1;
    unpk2(acc0, x0, x1); unpk2(acc1, y0, y1);
    g_em[(size_t)(bt0 + r) * Kk + k] = ((x0 + x1) + (y0 + y1)) + cb_s[k];
}

// =====================================================================
// Kernel D: CRF logZ, linear space, R2 loop shape (unroll 4, 4-deep em
// ring), renorm every 4 steps. Per-step chain: shfl-dot + 1 mul.
// =====================================================================
__global__ void crf_logz(const float* __restrict__ trans, float* __restrict__ out)
{
    const float L2E = 1.4426950408889634f, LN2 = 0.6931471805599453f;
    const int b = blockIdx.x;
    const int k = threadIdx.x;
    const unsigned full = 0xffffffffu;

    float Ecol[Kk];
#pragma unroll
    for (int jj = 0; jj < Kk; jj++)
        Ecol[jj] = ex2f(trans[jj * Kk + k] * L2E);

    const float* em = g_em + (size_t)b * Tt * Kk;

    float f0 = ex2f(em[1 * Kk + k] * L2E);
    float f1 = ex2f(em[2 * Kk + k] * L2E);
    float f2 = ex2f(em[3 * Kk + k] * L2E);
    float f3 = ex2f(em[4 * Kk + k] * L2E);

    float e0 = em[k];
    float m0 = __shfl_sync(full, e0, 0);
    float v  = ex2f((e0 - m0) * L2E);
    float Ml = m0 * L2E;

#pragma unroll 4
    for (int t = 1; t < Tt; t++) {
        float ut = f0; f0 = f1; f1 = f2; f2 = f3;
        int tp = t + 4;
        f3 = (tp < Tt) ? ex2f(em[(size_t)tp * Kk + k] * L2E) : 1.0f;

        float s0 = 0.f, s1 = 0.f, s2 = 0.f, s3 = 0.f;
#pragma unroll
        for (int j = 0; j < Kk; j += 4) {
            s0 += __shfl_sync(full, v, j    ) * Ecol[j    ];
            s1 += __shfl_sync(full, v, j + 1) * Ecol[j + 1];
            s2 += __shfl_sync(full, v, j + 2) * Ecol[j + 2];
            s3 += __shfl_sync(full, v, j + 3) * Ecol[j + 3];
        }
        v = ((s0 + s1) + (s2 + s3)) * ut;
        if ((t & 3) == 0) {                       // lazy renormalization
            float p0 = __shfl_sync(full, v, 0);
            v *= rcpf(p0);
            Ml += lg2f(p0);
        }
    }

    float sv = v;
#pragma unroll
    for (int o = 16; o; o >>= 1) sv += __shfl_xor_sync(full, sv, o);
    if (k == 0) out[b] = (Ml + lg2f(sv)) * LN2;
}

// =====================================================================
extern "C" void kernel_launch(void* const* d_in, const int* in_sizes, int n_in,
                              void* d_out, int out_size)
{
    const int*   tokens = (const int*)  d_in[0];
    const float* emb    = (const float*)d_in[1];
    const float* Wk_f   = (const float*)d_in[2];
    const float* Wr_f   = (const float*)d_in[3];
    const float* b_f    = (const float*)d_in[4];
    const float* Wk_b   = (const float*)d_in[5];
    const float* Wr_b   = (const float*)d_in[6];
    const float* b_b    = (const float*)d_in[7];
    const float* ck     = (const float*)d_in[8];
    const float* cb     = (const float*)d_in[9];
    const float* trans  = (const float*)d_in[10];
    float* out = (float*)d_out;

    cudaFuncSetAttribute(input_gemm, cudaFuncAttributeMaxDynamicSharedMemorySize, SMEM_A);
    cudaFuncSetAttribute(lstm_rec,   cudaFuncAttributeMaxDynamicSharedMemorySize, SMEM_B);

    input_gemm<<<dim3(BT / 128, 8), 256, SMEM_A>>>(tokens, emb, Wk_f, b_f, Wk_b, b_b);
    lstm_rec<<<128, 512, SMEM_B>>>(Wr_f, Wr_b);
    em_gemm<<<BT / 8, 256>>>(ck, cb);
    crf_logz<<<Bb, 32>>>(trans, out);
}